// round 12
// baseline (speedup 1.0000x reference)
#include <cuda_runtime.h>
#include <cstdint>

#define H 4096
#define HH (H * H)                  // 16777216
#define OUT_ACT  0
#define OUT_VAL  4
#define OUT_HACT 5
#define OUT_HEBB 4101               // hebb_new[H*H] (float offset 4101 == 1 mod 4)
#define NC   ((HH - 4) / 4 + 1)     // 4194303 valid output chunks (k = 4q+3)
#define HB4N (HH / 4)               // 4194304 float4 elements in hebb

__device__ float  g_y[H];
__device__ float  g_hact[H];
__device__ float4 g_hs4[1023];      // g_hs4[m] = hact[4m+3 .. 4m+6]
__device__ float  g_head[5];

// ---------------- bulk-async helpers ---------------------------------------
__device__ __forceinline__ uint32_t smem_u32(const void* p) {
    return (uint32_t)__cvta_generic_to_shared(p);
}
#define MBAR_INIT(mb, cnt) \
    asm volatile("mbarrier.init.shared.b64 [%0], %1;" :: "r"(mb), "r"(cnt) : "memory")
#define MBAR_EXPECT_TX(mb, bytes) \
    asm volatile("mbarrier.arrive.expect_tx.shared.b64 _, [%0], %1;" :: "r"(mb), "r"(bytes) : "memory")
#define BULK_G2S_POL(dst, src, bytes, mb, pol) \
    asm volatile("cp.async.bulk.shared::cluster.global.mbarrier::complete_tx::bytes.L2::cache_hint" \
                 " [%0], [%1], %2, [%3], %4;" \
                 :: "r"(dst), "l"(src), "r"(bytes), "r"(mb), "l"(pol) : "memory")
#define BULK_G2S(dst, src, bytes, mb) \
    asm volatile("cp.async.bulk.shared::cluster.global.mbarrier::complete_tx::bytes [%0], [%1], %2, [%3];" \
                 :: "r"(dst), "l"(src), "r"(bytes), "r"(mb) : "memory")

__device__ __forceinline__ uint64_t policy_evict_last() {
    uint64_t p;
    asm("createpolicy.fractional.L2::evict_last.b64 %0, 1.0;" : "=l"(p));
    return p;
}
__device__ __forceinline__ uint64_t policy_evict_first() {
    uint64_t p;
    asm("createpolicy.fractional.L2::evict_first.b64 %0, 1.0;" : "=l"(p));
    return p;
}

__device__ __forceinline__ void mbar_wait(uint32_t mb, uint32_t phase) {
    uint32_t done;
    do {
        asm volatile(
            "{\n\t.reg .pred p;\n\t"
            "mbarrier.try_wait.parity.acquire.cta.shared::cta.b64 p, [%1], %2, 0x989680;\n\t"
            "selp.b32 %0, 1, 0, p;\n\t}"
            : "=r"(done) : "r"(mb), "r"(phase) : "memory");
    } while (!done);
}

// ---------------------------------------------------------------------------
// Kernel 0: y[j] = bi[j] + x @ Wi; zero g_head.
// ---------------------------------------------------------------------------
__global__ void init_y_kernel(const float* __restrict__ x,
                              const float* __restrict__ Wi,
                              const float* __restrict__ bi) {
    int j = blockIdx.x * blockDim.x + threadIdx.x;
    if (j < 5) g_head[j] = 0.0f;
    if (j >= H) return;
    float s = bi[j];
#pragma unroll
    for (int k = 0; k < 17; k++)
        s = fmaf(x[k], Wi[k * H + j], s);
    g_y[j] = s;
}

// ---------------------------------------------------------------------------
// Kernel 1: gemv via cp.async.bulk pipeline, WIDE stages (R11-proven, ~36us).
// ---------------------------------------------------------------------------
#define GNS 4
#define GROWS 32
#define GEMV_SMEM (64 + GNS * 24576)
__global__ void __launch_bounds__(512)
gemv_acc_kernel(const float* __restrict__ hidden,
                const float* __restrict__ w,
                const float* __restrict__ alpha,
                const float* __restrict__ hebb) {
    extern __shared__ char smem[];
    uint32_t mb0 = smem_u32(smem);                 // GNS mbarriers
    float* buf = (float*)(smem + 64);              // GNS * 6144 floats
    int t  = threadIdx.x;
    int cs = blockIdx.x;
    int r0 = blockIdx.y * GROWS;
    size_t cbase = (size_t)cs * 2048;
    size_t base0 = (size_t)r0 * H + cbase;
    uint64_t pol_wf = policy_evict_first();
    uint64_t pol_hb = policy_evict_last();

    if (t == 0) {
#pragma unroll
        for (int i = 0; i < GNS; i++) MBAR_INIT(mb0 + 8 * i, 1);
    }
    __syncthreads();

    auto issue = [&](int s) {                      // t0 only
        int b = s % GNS;
        size_t off = base0 + (size_t)s * H;
        uint32_t d = smem_u32(buf + b * 6144);
        uint32_t mb = mb0 + 8 * b;
        MBAR_EXPECT_TX(mb, 24576);
        BULK_G2S_POL(d,         w + off,     8192, mb, pol_wf);
        BULK_G2S_POL(d + 8192,  alpha + off, 8192, mb, pol_wf);
        BULK_G2S_POL(d + 16384, hebb + off,  8192, mb, pol_hb);
    };

    if (t == 0) {
#pragma unroll
        for (int s = 0; s < GNS; s++) issue(s);
    }

    float4 acc = make_float4(0.f, 0.f, 0.f, 0.f);
    for (int s = 0; s < GROWS; s++) {
        int b = s % GNS;
        mbar_wait(mb0 + 8 * b, (uint32_t)((s / GNS) & 1));
        const float4* fb = (const float4*)(buf + b * 6144);
        float4 wv = fb[t];
        float4 av = fb[512 + t];
        float4 hv = fb[1024 + t];
        float  hval = __ldg(hidden + r0 + s);
        acc.x = fmaf(hval, fmaf(av.x, hv.x, wv.x), acc.x);
        acc.y = fmaf(hval, fmaf(av.y, hv.y, wv.y), acc.y);
        acc.z = fmaf(hval, fmaf(av.z, hv.z, wv.z), acc.z);
        acc.w = fmaf(hval, fmaf(av.w, hv.w, wv.w), acc.w);
        __syncthreads();                           // everyone done with buf b
        if (t == 0 && s + GNS < GROWS) issue(s + GNS);
    }
    int j = (int)cbase + t * 4;
    atomicAdd(&g_y[j + 0], acc.x);
    atomicAdd(&g_y[j + 1], acc.y);
    atomicAdd(&g_y[j + 2], acc.z);
    atomicAdd(&g_y[j + 3], acc.w);
}

// ---------------------------------------------------------------------------
// Kernel 2: hactiv = tanh(y); heads partials; g_hact/g_hs4 views.
// ---------------------------------------------------------------------------
__inline__ __device__ float warp_sum(float v) {
#pragma unroll
    for (int o = 16; o > 0; o >>= 1)
        v += __shfl_down_sync(0xffffffffu, v, o);
    return v;
}

__global__ void __launch_bounds__(128)
finalize_kernel(const float* __restrict__ Wo,
                const float* __restrict__ Wv,
                float* __restrict__ out) {
    int t = threadIdx.x;
    int j = blockIdx.x * 128 + t;
    float hact = tanhf(g_y[j]);
    out[OUT_HACT + j] = hact;
    g_hact[j] = hact;

    int r = j & 3;
    if (r == 3)      { if (j <= 4091) g_hs4[(j - 3) >> 2].x = hact; }
    else if (r == 0) { if (j >= 4)    g_hs4[(j - 4) >> 2].y = hact; }
    else if (r == 1) { if (j >= 5)    g_hs4[(j - 5) >> 2].z = hact; }
    else             { if (j >= 6)    g_hs4[(j - 6) >> 2].w = hact; }

    float4 wo = *(const float4*)(Wo + (size_t)j * 4);
    float p0 = hact * wo.x, p1 = hact * wo.y;
    float p2 = hact * wo.z, p3 = hact * wo.w;
    float pv = hact * Wv[j];

    __shared__ float sh[5][4];
    int lane = t & 31, wid = t >> 5;
    p0 = warp_sum(p0); p1 = warp_sum(p1); p2 = warp_sum(p2);
    p3 = warp_sum(p3); pv = warp_sum(pv);
    if (lane == 0) {
        sh[0][wid] = p0; sh[1][wid] = p1; sh[2][wid] = p2;
        sh[3][wid] = p3; sh[4][wid] = pv;
    }
    __syncthreads();
    if (t < 5)
        atomicAdd(&g_head[t], sh[t][0] + sh[t][1] + sh[t][2] + sh[t][3]);
}

// ---------------------------------------------------------------------------
// Kernel 3: hebb update, TMA-read + direct-STG-write.
// Reads ride the TMA engine (6-deep ring of 8208B tiles; +16B covers the
// 1-float shift so no overlap LDGs). Stores are direct __stcs STG.128 —
// no out staging, no store-ordering waits (R5's mistakes removed).
// 49KB smem -> 4 blocks/SM (50% occ). grid 1024 x 8 stages x 512 chunks.
// ---------------------------------------------------------------------------
#define HNS 6
#define HSTG 8
#define HEBB_SMEM (64 + HNS * 8208)
__global__ void __launch_bounds__(256)
hebb_update_kernel(const float* __restrict__ hebb,
                   const float* __restrict__ hidden,
                   const float* __restrict__ eta,
                   const float* __restrict__ bo,
                   const float* __restrict__ bv,
                   float* __restrict__ out) {
    extern __shared__ char smem[];
    uint32_t mb0 = smem_u32(smem);
    float4* ibuf = (float4*)(smem + 64);           // HNS * 513 float4
    int t = threadIdx.x;
    float et = __ldg(eta);
    float em = 1.0f - et;
    float* ho = out + OUT_HEBB;
    const float4* hb4 = (const float4*)hebb;
    long long B0 = (long long)blockIdx.x * HSTG;   // first stage id of block

    if (t == 0) {
#pragma unroll
        for (int i = 0; i < HNS; i++) MBAR_INIT(mb0 + 8 * i, 1);
    }
    __syncthreads();

    if (blockIdx.x == 0 && t == 0) {
        // boundary scalars + heads (finalize has completed)
#pragma unroll
        for (int k = 0; k < 3; k++)
            ho[k] = fmaf(em, hebb[k], et * hidden[0] * g_hact[k]);
        ho[HH - 1] = fmaf(em, hebb[HH - 1], et * hidden[H - 1] * g_hact[H - 1]);
        float l0 = g_head[0] + bo[0], l1 = g_head[1] + bo[1];
        float l2 = g_head[2] + bo[2], l3 = g_head[3] + bo[3];
        float m = fmaxf(fmaxf(l0, l1), fmaxf(l2, l3));
        float e0 = expf(l0 - m), e1 = expf(l1 - m);
        float e2 = expf(l2 - m), e3 = expf(l3 - m);
        float inv = 1.0f / (e0 + e1 + e2 + e3);
        out[OUT_ACT + 0] = e0 * inv;
        out[OUT_ACT + 1] = e1 * inv;
        out[OUT_ACT + 2] = e2 * inv;
        out[OUT_ACT + 3] = e3 * inv;
        out[OUT_VAL] = g_head[4] + bv[0];
    }

    auto issue = [&](int s) {                      // t0 only
        int b = s % HNS;
        long long Q0 = (B0 + s) * 512;
        uint32_t bytes = (Q0 + 513 <= (long long)HB4N) ? 8208u : 8192u;
        uint32_t mb = mb0 + 8 * b;
        MBAR_EXPECT_TX(mb, bytes);
        BULK_G2S(smem_u32(ibuf + b * 513), hb4 + Q0, bytes, mb);
    };

    if (t == 0) {
#pragma unroll
        for (int s = 0; s < HNS; s++) issue(s);
    }

#pragma unroll
    for (int s = 0; s < HSTG; s++) {
        int b = s % HNS;
        long long Q0 = (B0 + s) * 512;
        mbar_wait(mb0 + 8 * b, (uint32_t)((s / HNS) & 1));
        const float4* in = ibuf + b * 513;
#pragma unroll
        for (int u = 0; u < 2; u++) {
            int c = t + u * 256;
            long long q = Q0 + c;
            if (q >= NC) break;
            float4 A = in[c];
            float4 Bv = in[c + 1];
            float s0 = A.w, s1 = Bv.x, s2 = Bv.y, s3 = Bv.z;
            int i0 = (int)(q >> 10);
            int jm = (int)(q & 1023);              // j0 = 4*jm + 3
            float4 r;
            if (jm != 1023) {
                float hi = __ldg(hidden + i0) * et;
                float4 g = g_hs4[jm];              // hact[j0 .. j0+3]
                r.x = fmaf(em, s0, hi * g.x);
                r.y = fmaf(em, s1, hi * g.y);
                r.z = fmaf(em, s2, hi * g.z);
                r.w = fmaf(em, s3, hi * g.w);
            } else {                               // row-boundary chunk
                long long k = 4 * q + 3;
                float src[4] = {s0, s1, s2, s3};
                float rr[4];
#pragma unroll
                for (int e = 0; e < 4; e++) {
                    long long kk = k + e;
                    int i = (int)(kk >> 12);
                    int jj = (int)(kk & (H - 1));
                    rr[e] = fmaf(em, src[e], et * __ldg(hidden + i) * g_hact[jj]);
                }
                r = make_float4(rr[0], rr[1], rr[2], rr[3]);
            }
            __stcs((float4*)(ho + 4 * q + 3), r);  // direct streaming STG.128
        }
        __syncthreads();                           // buffer b fully consumed
        if (t == 0 && s + HNS < HSTG) issue(s + HNS);
    }
}

// ---------------------------------------------------------------------------
extern "C" void kernel_launch(void* const* d_in, const int* in_sizes, int n_in,
                              void* d_out, int out_size) {
    const float* x      = (const float*)d_in[0];
    const float* hidden = (const float*)d_in[1];
    const float* hebb   = (const float*)d_in[2];
    const float* Wi     = (const float*)d_in[3];
    const float* bi     = (const float*)d_in[4];
    const float* w      = (const float*)d_in[5];
    const float* alpha  = (const float*)d_in[6];
    const float* eta    = (const float*)d_in[7];
    const float* Wo     = (const float*)d_in[8];
    const float* bo     = (const float*)d_in[9];
    const float* Wv     = (const float*)d_in[10];
    const float* bv     = (const float*)d_in[11];
    float* out = (float*)d_out;

    cudaFuncSetAttribute(gemv_acc_kernel,
                         cudaFuncAttributeMaxDynamicSharedMemorySize, GEMV_SMEM);
    cudaFuncSetAttribute(hebb_update_kernel,
                         cudaFuncAttributeMaxDynamicSharedMemorySize, HEBB_SMEM);

    init_y_kernel<<<H / 256, 256>>>(x, Wi, bi);
    gemv_acc_kernel<<<dim3(2, 128), 512, GEMV_SMEM>>>(hidden, w, alpha, hebb);
    finalize_kernel<<<32, 128>>>(Wo, Wv, out);
    hebb_update_kernel<<<1024, 256, HEBB_SMEM>>>(hebb, hidden, eta, bo, bv, out);
}

// round 13
// speedup vs baseline: 1.0689x; 1.0689x over previous
#include <cuda_runtime.h>
#include <cstdint>

#define H 4096
#define HH (H * H)                  // 16777216
#define OUT_ACT  0
#define OUT_VAL  4
#define OUT_HACT 5
#define OUT_HEBB 4101               // hebb_new[H*H] (float offset 4101 == 1 mod 4)
#define NC   ((HH - 4) / 4 + 1)     // 4194303 valid output chunks (k = 4q+3)

__device__ float  g_y[H];           // zero at module load; finalize re-zeroes after read
__device__ float  g_hact[H];
__device__ float4 g_hs4[1023];      // g_hs4[m] = hact[4m+3 .. 4m+6]
__device__ float  g_head[5];        // zero at module load; hebb block0 re-zeroes after read

// ---------------- bulk-async helpers ---------------------------------------
__device__ __forceinline__ uint32_t smem_u32(const void* p) {
    return (uint32_t)__cvta_generic_to_shared(p);
}
#define MBAR_INIT(mb, cnt) \
    asm volatile("mbarrier.init.shared.b64 [%0], %1;" :: "r"(mb), "r"(cnt) : "memory")
#define MBAR_EXPECT_TX(mb, bytes) \
    asm volatile("mbarrier.arrive.expect_tx.shared.b64 _, [%0], %1;" :: "r"(mb), "r"(bytes) : "memory")
#define BULK_G2S_POL(dst, src, bytes, mb, pol) \
    asm volatile("cp.async.bulk.shared::cluster.global.mbarrier::complete_tx::bytes.L2::cache_hint" \
                 " [%0], [%1], %2, [%3], %4;" \
                 :: "r"(dst), "l"(src), "r"(bytes), "r"(mb), "l"(pol) : "memory")

__device__ __forceinline__ uint64_t policy_evict_last() {
    uint64_t p;
    asm("createpolicy.fractional.L2::evict_last.b64 %0, 1.0;" : "=l"(p));
    return p;
}
__device__ __forceinline__ uint64_t policy_evict_first() {
    uint64_t p;
    asm("createpolicy.fractional.L2::evict_first.b64 %0, 1.0;" : "=l"(p));
    return p;
}

__device__ __forceinline__ void mbar_wait(uint32_t mb, uint32_t phase) {
    uint32_t done;
    do {
        asm volatile(
            "{\n\t.reg .pred p;\n\t"
            "mbarrier.try_wait.parity.acquire.cta.shared::cta.b64 p, [%1], %2, 0x989680;\n\t"
            "selp.b32 %0, 1, 0, p;\n\t}"
            : "=r"(done) : "r"(mb), "r"(phase) : "memory");
    } while (!done);
}

// ---------------------------------------------------------------------------
// Kernel 1: gemv via cp.async.bulk pipeline, WIDE stages (R11-proven, ~36us).
//   w/alpha -> evict_first (dead after); hebb -> evict_last (pins L2).
// grid (2, 128): 2048-float column strip x 32 rows = 256 blocks of 512 thr.
// ---------------------------------------------------------------------------
#define GNS 4
#define GROWS 32
#define GEMV_SMEM (64 + GNS * 24576)
__global__ void __launch_bounds__(512)
gemv_acc_kernel(const float* __restrict__ hidden,
                const float* __restrict__ w,
                const float* __restrict__ alpha,
                const float* __restrict__ hebb) {
    extern __shared__ char smem[];
    uint32_t mb0 = smem_u32(smem);                 // GNS mbarriers
    float* buf = (float*)(smem + 64);              // GNS * 6144 floats
    int t  = threadIdx.x;
    int cs = blockIdx.x;
    int r0 = blockIdx.y * GROWS;
    size_t cbase = (size_t)cs * 2048;
    size_t base0 = (size_t)r0 * H + cbase;
    uint64_t pol_wf = policy_evict_first();
    uint64_t pol_hb = policy_evict_last();

    if (t == 0) {
#pragma unroll
        for (int i = 0; i < GNS; i++) MBAR_INIT(mb0 + 8 * i, 1);
    }
    __syncthreads();

    auto issue = [&](int s) {                      // t0 only
        int b = s % GNS;
        size_t off = base0 + (size_t)s * H;
        uint32_t d = smem_u32(buf + b * 6144);
        uint32_t mb = mb0 + 8 * b;
        MBAR_EXPECT_TX(mb, 24576);
        BULK_G2S_POL(d,         w + off,     8192, mb, pol_wf);
        BULK_G2S_POL(d + 8192,  alpha + off, 8192, mb, pol_wf);
        BULK_G2S_POL(d + 16384, hebb + off,  8192, mb, pol_hb);
    };

    if (t == 0) {
#pragma unroll
        for (int s = 0; s < GNS; s++) issue(s);
    }

    float4 acc = make_float4(0.f, 0.f, 0.f, 0.f);
    for (int s = 0; s < GROWS; s++) {
        int b = s % GNS;
        mbar_wait(mb0 + 8 * b, (uint32_t)((s / GNS) & 1));
        const float4* fb = (const float4*)(buf + b * 6144);
        float4 wv = fb[t];
        float4 av = fb[512 + t];
        float4 hv = fb[1024 + t];
        float  hval = __ldg(hidden + r0 + s);
        acc.x = fmaf(hval, fmaf(av.x, hv.x, wv.x), acc.x);
        acc.y = fmaf(hval, fmaf(av.y, hv.y, wv.y), acc.y);
        acc.z = fmaf(hval, fmaf(av.z, hv.z, wv.z), acc.z);
        acc.w = fmaf(hval, fmaf(av.w, hv.w, wv.w), acc.w);
        __syncthreads();                           // everyone done with buf b
        if (t == 0 && s + GNS < GROWS) issue(s + GNS);
    }
    int j = (int)cbase + t * 4;
    atomicAdd(&g_y[j + 0], acc.x);
    atomicAdd(&g_y[j + 1], acc.y);
    atomicAdd(&g_y[j + 2], acc.z);
    atomicAdd(&g_y[j + 3], acc.w);
}

// ---------------------------------------------------------------------------
// Kernel 2: hactiv = tanh(g_y + bi + x@Wi); re-zero g_y for next replay;
// heads partials; g_hact/g_hs4 views. (init kernel eliminated.)
// ---------------------------------------------------------------------------
__inline__ __device__ float warp_sum(float v) {
#pragma unroll
    for (int o = 16; o > 0; o >>= 1)
        v += __shfl_down_sync(0xffffffffu, v, o);
    return v;
}

__global__ void __launch_bounds__(128)
finalize_kernel(const float* __restrict__ x,
                const float* __restrict__ Wi,
                const float* __restrict__ bi,
                const float* __restrict__ Wo,
                const float* __restrict__ Wv,
                float* __restrict__ out) {
    int t = threadIdx.x;
    int j = blockIdx.x * 128 + t;
    float s = g_y[j] + bi[j];
    g_y[j] = 0.0f;                    // reset accumulator for next replay
#pragma unroll
    for (int k = 0; k < 17; k++)
        s = fmaf(__ldg(x + k), Wi[k * H + j], s);   // coalesced across j
    float hact = tanhf(s);
    out[OUT_HACT + j] = hact;
    g_hact[j] = hact;

    int r = j & 3;
    if (r == 3)      { if (j <= 4091) g_hs4[(j - 3) >> 2].x = hact; }
    else if (r == 0) { if (j >= 4)    g_hs4[(j - 4) >> 2].y = hact; }
    else if (r == 1) { if (j >= 5)    g_hs4[(j - 5) >> 2].z = hact; }
    else             { if (j >= 6)    g_hs4[(j - 6) >> 2].w = hact; }

    float4 wo = *(const float4*)(Wo + (size_t)j * 4);
    float p0 = hact * wo.x, p1 = hact * wo.y;
    float p2 = hact * wo.z, p3 = hact * wo.w;
    float pv = hact * Wv[j];

    __shared__ float sh[5][4];
    int lane = t & 31, wid = t >> 5;
    p0 = warp_sum(p0); p1 = warp_sum(p1); p2 = warp_sum(p2);
    p3 = warp_sum(p3); pv = warp_sum(pv);
    if (lane == 0) {
        sh[0][wid] = p0; sh[1][wid] = p1; sh[2][wid] = p2;
        sh[3][wid] = p3; sh[4][wid] = pv;
    }
    __syncthreads();
    if (t < 5)
        atomicAdd(&g_head[t], sh[t][0] + sh[t][1] + sh[t][2] + sh[t][3]);
}

// ---------------------------------------------------------------------------
// Kernel 3: hebb update — proven LDG grid-stride version (~21.3us).
// Block 0 emits heads from g_head (reading ALL of it first), then re-zeroes.
// ---------------------------------------------------------------------------
__global__ void __launch_bounds__(256)
hebb_update_kernel(const float* __restrict__ hebb,
                   const float* __restrict__ hidden,
                   const float* __restrict__ eta,
                   const float* __restrict__ bo,
                   const float* __restrict__ bv,
                   float* __restrict__ out) {
    const long long STRIDE = 2048LL * 256LL;   // 524288 threads, 8 chunks each
    long long tid = (long long)blockIdx.x * 256 + threadIdx.x;
    float et = __ldg(eta);
    float em = 1.0f - et;
    float* ho = out + OUT_HEBB;
    const float4* hb4 = (const float4*)hebb;

    if (blockIdx.x == 0 && threadIdx.x == 0) {
#pragma unroll
        for (int k = 0; k < 3; k++)
            ho[k] = fmaf(em, hebb[k], et * hidden[0] * g_hact[k]);
        ho[HH - 1] = fmaf(em, hebb[HH - 1], et * hidden[H - 1] * g_hact[H - 1]);
        // read ALL head sums first, then reset for the next replay
        float l0 = g_head[0] + bo[0], l1 = g_head[1] + bo[1];
        float l2 = g_head[2] + bo[2], l3 = g_head[3] + bo[3];
        float vsum = g_head[4];
#pragma unroll
        for (int k = 0; k < 5; k++) g_head[k] = 0.0f;
        float m = fmaxf(fmaxf(l0, l1), fmaxf(l2, l3));
        float e0 = expf(l0 - m), e1 = expf(l1 - m);
        float e2 = expf(l2 - m), e3 = expf(l3 - m);
        float inv = 1.0f / (e0 + e1 + e2 + e3);
        out[OUT_ACT + 0] = e0 * inv;
        out[OUT_ACT + 1] = e1 * inv;
        out[OUT_ACT + 2] = e2 * inv;
        out[OUT_ACT + 3] = e3 * inv;
        out[OUT_VAL] = vsum + bv[0];
    }

#pragma unroll 2
    for (int e = 0; e < 8; e++) {
        long long q = tid + (long long)e * STRIDE;
        if (q >= NC) break;
        float4 A = hb4[q];
        float4 B = hb4[q + 1];                // same/adjacent 128B line
        float s0 = A.w, s1 = B.x, s2 = B.y, s3 = B.z;

        long long k = 4 * q + 3;
        int i0 = (int)(k >> 12);
        int j0 = (int)(k & (H - 1));
        float4 r;
        if (j0 != H - 1) {
            float hi = __ldg(hidden + i0) * et;
            float4 g = g_hs4[j0 >> 2];        // hact[j0 .. j0+3], one LDG.128
            r.x = fmaf(em, s0, hi * g.x);
            r.y = fmaf(em, s1, hi * g.y);
            r.z = fmaf(em, s2, hi * g.z);
            r.w = fmaf(em, s3, hi * g.w);
        } else {
            float src[4] = {s0, s1, s2, s3};
            float rr[4];
#pragma unroll
            for (int u = 0; u < 4; u++) {
                long long kk = k + u;
                int i = (int)(kk >> 12);
                int jj = (int)(kk & (H - 1));
                rr[u] = fmaf(em, src[u], et * __ldg(hidden + i) * g_hact[jj]);
            }
            r = make_float4(rr[0], rr[1], rr[2], rr[3]);
        }
        __stcs((float4*)(ho + k), r);         // 16B-aligned streaming store
    }
}

// ---------------------------------------------------------------------------
extern "C" void kernel_launch(void* const* d_in, const int* in_sizes, int n_in,
                              void* d_out, int out_size) {
    const float* x      = (const float*)d_in[0];
    const float* hidden = (const float*)d_in[1];
    const float* hebb   = (const float*)d_in[2];
    const float* Wi     = (const float*)d_in[3];
    const float* bi     = (const float*)d_in[4];
    const float* w      = (const float*)d_in[5];
    const float* alpha  = (const float*)d_in[6];
    const float* eta    = (const float*)d_in[7];
    const float* Wo     = (const float*)d_in[8];
    const float* bo     = (const float*)d_in[9];
    const float* Wv     = (const float*)d_in[10];
    const float* bv     = (const float*)d_in[11];
    float* out = (float*)d_out;

    cudaFuncSetAttribute(gemv_acc_kernel,
                         cudaFuncAttributeMaxDynamicSharedMemorySize, GEMV_SMEM);

    gemv_acc_kernel<<<dim3(2, 128), 512, GEMV_SMEM>>>(hidden, w, alpha, hebb);
    finalize_kernel<<<32, 128>>>(x, Wi, bi, Wo, Wv, out);
    hebb_update_kernel<<<2048, 256>>>(hebb, hidden, eta, bo, bv, out);
}